// round 3
// baseline (speedup 1.0000x reference)
#include <cuda_runtime.h>

// Izhikevich RS constants (match reference)
#define P_A 0.02f
#define P_B 0.2f
#define P_C (-65.0f)
#define P_D 8.0f
#define I_TONIC (-3.0f)
// W_rec: diag = 4.0, offdiag = -2.0  =>  I_rec[i] = 6*r[i] - 2*sum(r)

struct SimState {
    float v[4], u[4], r[4], cnt[4];
};

__device__ __forceinline__ void sim_step(SimState& st, const float* __restrict__ Ip)
{
    const float rsum = st.r[0] + st.r[1] + st.r[2] + st.r[3];
    #pragma unroll
    for (int i = 0; i < 4; i++) {
        const float I = Ip[i] + 6.0f * st.r[i] - 2.0f * rsum;
        float vn = fmaf(0.04f * st.v[i], st.v[i],
                        fmaf(6.0f, st.v[i], 140.0f - st.u[i] + I));
        float un = st.u[i] + P_A * fmaf(P_B, st.v[i], -st.u[i]);
        const float sp = (vn >= 30.0f) ? 1.0f : 0.0f;
        if (sp > 0.0f) { vn = P_C; un += P_D; }
        st.r[i]   = fmaf(0.9f, st.r[i], 0.1f * sp);
        st.cnt[i] += sp;
        st.v[i] = vn; st.u[i] = un;
    }
}

__global__ void __launch_bounds__(256, 1)
spiking_goal_selector_kernel(
    const float* __restrict__ pal_d_rate,   // (3072,)
    const float* __restrict__ neuromod_bias,// (4,)
    const float* __restrict__ W,            // (4, 3072) row-major
    const int*   __restrict__ substeps_p,   // scalar
    float* __restrict__ out, int out_size, int n_e)
{
    __shared__ float part[8];   // one partial per warp

    const int warp = threadIdx.x >> 5;
    const int lane = threadIdx.x & 31;

    // ---- hoist scalar loads: issued at entry, consumed after barrier ----
    int   T  = 0;
    float b0 = 0.f, b1 = 0.f, b2 = 0.f, b3 = 0.f;
    if (threadIdx.x == 0) {
        T  = *substeps_p;
        b0 = neuromod_bias[0];
        b1 = neuromod_bias[1];
        b2 = neuromod_bias[2];
        b3 = neuromod_bias[3];
    }

    // ---- matvec: 8 warps, 2 per row; 12 float4 per lane, fully unrolled ----
    // n_e = 3072 -> nv4 = 768, q = 384 per warp-slice, 12 float4/lane ->
    // 24 independent LDG.128 in flight per lane, one DRAM wave for all of W.
    const int row = warp >> 1;
    const int p   = warp & 1;
    const int nv4 = n_e >> 2;
    const int q   = nv4 >> 1;          // float4s per warp-slice
    const float4* Wr = reinterpret_cast<const float4*>(W + (size_t)row * n_e) + p * q;
    const float4* xr = reinterpret_cast<const float4*>(pal_d_rate) + p * q;

    float s = 0.0f;
    #pragma unroll 12
    for (int i = lane; i < q; i += 32) {
        float4 w = Wr[i];
        float4 x = xr[i];
        s += w.x * x.x + w.y * x.y + w.z * x.z + w.w * x.w;
    }
    #pragma unroll
    for (int o = 16; o > 0; o >>= 1)
        s += __shfl_down_sync(0xffffffffu, s, o);
    if (lane == 0) part[warp] = s;
    __syncthreads();

    // ---- serial WTA dynamics on thread 0 (4 neurons, T steps) ----
    if (threadIdx.x == 0) {
        float Ip[4];
        float m = 0.0f;
        #pragma unroll
        for (int i = 0; i < 4; i++) {
            Ip[i] = part[2*i] + part[2*i+1];
            m += fabsf(Ip[i]);
        }
        m = m * 0.25f + 1e-8f;
        const float scale = (m > 1e-3f) ? (3.0f / m) : 0.0f;
        const float bias[4] = {b0, b1, b2, b3};
        #pragma unroll
        for (int i = 0; i < 4; i++)
            Ip[i] = fmaf(Ip[i], scale, fmaf(bias[i], 2.0f, I_TONIC));

        SimState st;
        #pragma unroll
        for (int i = 0; i < 4; i++) {
            st.v[i] = P_C; st.u[i] = P_B * P_C; st.r[i] = 0.0f; st.cnt[i] = 0.0f;
        }

        if (T == 30) {
            // compile-time trip count: no loop bookkeeping, deep scheduling
            #pragma unroll 6
            for (int t = 0; t < 30; t++) sim_step(st, Ip);
        } else {
            for (int t = 0; t < T; t++) sim_step(st, Ip);
        }

        const float invT = 1.0f / (float)T;
        float4 rates;
        rates.x = st.cnt[0] * invT;
        rates.y = st.cnt[1] * invT;
        rates.z = st.cnt[2] * invT;
        rates.w = st.cnt[3] * invT;
        const float rsum2 = rates.x + rates.y + rates.z + rates.w;

        int win = 0; float best = rates.x;
        if (rates.y > best) { best = rates.y; win = 1; }
        if (rates.z > best) { best = rates.z; win = 2; }
        if (rates.w > best) { best = rates.w; win = 3; }

        // Output layout: [rates(4), winner, confidence]
        if (out_size >= 6) {
            *reinterpret_cast<float4*>(out) = rates;
            out[4] = (float)win;
            out[5] = best / (rsum2 + 1e-8f);
        } else {
            float rr[4] = {rates.x, rates.y, rates.z, rates.w};
            for (int i = 0; i < 4 && i < out_size; i++) out[i] = rr[i];
            if (out_size > 4) out[4] = (float)win;
            if (out_size > 5) out[5] = best / (rsum2 + 1e-8f);
        }
    }
}

extern "C" void kernel_launch(void* const* d_in, const int* in_sizes, int n_in,
                              void* d_out, int out_size)
{
    const float* pal_d_rate    = (const float*)d_in[0];   // 3072
    const float* neuromod_bias = (const float*)d_in[1];   // 4
    const float* W_pald_goal   = (const float*)d_in[2];   // 4*3072
    const int*   substeps      = (const int*)  d_in[3];   // 1
    float* out = (float*)d_out;
    const int n_e = in_sizes[0];

    spiking_goal_selector_kernel<<<1, 256>>>(
        pal_d_rate, neuromod_bias, W_pald_goal, substeps, out, out_size, n_e);
}

// round 4
// speedup vs baseline: 1.0246x; 1.0246x over previous
#include <cuda_runtime.h>

// Izhikevich RS constants (match reference)
#define P_A 0.02f
#define P_B 0.2f
#define P_C (-65.0f)
#define P_D 8.0f
#define I_TONIC (-3.0f)
// W_rec: diag = 4.0, offdiag = -2.0  =>  I_rec[i] = 6*r[i] - 2*sum(r)

struct SimState {
    float v[4], u[4], r[4], cnt[4];
};

__device__ __forceinline__ void sim_step(SimState& st, const float* __restrict__ Ip)
{
    const float rsum = st.r[0] + st.r[1] + st.r[2] + st.r[3];
    #pragma unroll
    for (int i = 0; i < 4; i++) {
        const float I = Ip[i] + 6.0f * st.r[i] - 2.0f * rsum;
        float vn = fmaf(0.04f * st.v[i], st.v[i],
                        fmaf(6.0f, st.v[i], 140.0f - st.u[i] + I));
        float un = st.u[i] + P_A * fmaf(P_B, st.v[i], -st.u[i]);
        const float sp = (vn >= 30.0f) ? 1.0f : 0.0f;
        if (sp > 0.0f) { vn = P_C; un += P_D; }
        st.r[i]   = fmaf(0.9f, st.r[i], 0.1f * sp);
        st.cnt[i] += sp;
        st.v[i] = vn; st.u[i] = un;
    }
}

__global__ void __launch_bounds__(512, 1)
spiking_goal_selector_kernel(
    const float* __restrict__ pal_d_rate,   // (3072,)
    const float* __restrict__ neuromod_bias,// (4,)
    const float* __restrict__ W,            // (4, 3072) row-major
    const int*   __restrict__ substeps_p,   // scalar
    float* __restrict__ out, int out_size, int n_e)
{
    __shared__ float part[16];   // one partial per warp

    const int warp = threadIdx.x >> 5;
    const int lane = threadIdx.x & 31;

    // ---- hoist scalar loads: issued at entry, consumed after barrier ----
    int   T  = 0;
    float b0 = 0.f, b1 = 0.f, b2 = 0.f, b3 = 0.f;
    if (threadIdx.x == 0) {
        T  = *substeps_p;
        b0 = neuromod_bias[0];
        b1 = neuromod_bias[1];
        b2 = neuromod_bias[2];
        b3 = neuromod_bias[3];
    }

    // ---- matvec (measured-best config): 16 warps, 4 per row,
    //      6 fully-unrolled float4 per lane -> whole W in one load wave ----
    const int row = warp >> 2;
    const int p   = warp & 3;
    const int nv4 = n_e >> 2;
    const int q   = nv4 >> 2;          // float4s per warp-slice (192)
    const float4* Wr = reinterpret_cast<const float4*>(W + (size_t)row * n_e) + p * q;
    const float4* xr = reinterpret_cast<const float4*>(pal_d_rate) + p * q;

    float s = 0.0f;
    #pragma unroll 6
    for (int i = lane; i < q; i += 32) {
        float4 w = Wr[i];
        float4 x = xr[i];
        s += w.x * x.x + w.y * x.y + w.z * x.z + w.w * x.w;
    }
    #pragma unroll
    for (int o = 16; o > 0; o >>= 1)
        s += __shfl_down_sync(0xffffffffu, s, o);
    if (lane == 0) part[warp] = s;
    __syncthreads();

    // ---- serial WTA dynamics on thread 0 (4 neurons, T steps) ----
    if (threadIdx.x == 0) {
        float Ip[4];
        float m = 0.0f;
        #pragma unroll
        for (int i = 0; i < 4; i++) {
            Ip[i] = (part[4*i] + part[4*i+1]) + (part[4*i+2] + part[4*i+3]);
            m += fabsf(Ip[i]);
        }
        m = m * 0.25f + 1e-8f;
        const float scale = (m > 1e-3f) ? (3.0f / m) : 0.0f;
        const float bias[4] = {b0, b1, b2, b3};
        #pragma unroll
        for (int i = 0; i < 4; i++)
            Ip[i] = fmaf(Ip[i], scale, fmaf(bias[i], 2.0f, I_TONIC));

        SimState st;
        #pragma unroll
        for (int i = 0; i < 4; i++) {
            st.v[i] = P_C; st.u[i] = P_B * P_C; st.r[i] = 0.0f; st.cnt[i] = 0.0f;
        }

        if (T == 30) {
            // compile-time trip count: minimal loop bookkeeping
            #pragma unroll 6
            for (int t = 0; t < 30; t++) sim_step(st, Ip);
        } else {
            for (int t = 0; t < T; t++) sim_step(st, Ip);
        }

        const float invT = 1.0f / (float)T;
        float4 rates;
        rates.x = st.cnt[0] * invT;
        rates.y = st.cnt[1] * invT;
        rates.z = st.cnt[2] * invT;
        rates.w = st.cnt[3] * invT;
        const float rsum2 = (rates.x + rates.y) + (rates.z + rates.w);

        int win = 0; float best = rates.x;
        if (rates.y > best) { best = rates.y; win = 1; }
        if (rates.z > best) { best = rates.z; win = 2; }
        if (rates.w > best) { best = rates.w; win = 3; }

        // Output layout: [rates(4), winner, confidence]
        if (out_size >= 6) {
            *reinterpret_cast<float4*>(out) = rates;
            out[4] = (float)win;
            out[5] = best / (rsum2 + 1e-8f);
        } else {
            float rr[4] = {rates.x, rates.y, rates.z, rates.w};
            for (int i = 0; i < 4 && i < out_size; i++) out[i] = rr[i];
            if (out_size > 4) out[4] = (float)win;
            if (out_size > 5) out[5] = best / (rsum2 + 1e-8f);
        }
    }
}

extern "C" void kernel_launch(void* const* d_in, const int* in_sizes, int n_in,
                              void* d_out, int out_size)
{
    const float* pal_d_rate    = (const float*)d_in[0];   // 3072
    const float* neuromod_bias = (const float*)d_in[1];   // 4
    const float* W_pald_goal   = (const float*)d_in[2];   // 4*3072
    const int*   substeps      = (const int*)  d_in[3];   // 1
    float* out = (float*)d_out;
    const int n_e = in_sizes[0];

    spiking_goal_selector_kernel<<<1, 512>>>(
        pal_d_rate, neuromod_bias, W_pald_goal, substeps, out, out_size, n_e);
}

// round 5
// speedup vs baseline: 1.1013x; 1.0749x over previous
#include <cuda_runtime.h>

// Izhikevich RS constants (match reference)
#define P_A 0.02f
#define P_B 0.2f
#define P_C (-65.0f)
#define P_D 8.0f
#define I_TONIC (-3.0f)
// W_rec: diag = 4.0, offdiag = -2.0  =>  I_rec[i] = 6*r[i] - 2*sum(r)

struct SimState {
    float v[4], u[4], r[4], cnt[4];
};

__device__ __forceinline__ void sim_step(SimState& st, const float* __restrict__ Ip)
{
    const float rsum = (st.r[0] + st.r[1]) + (st.r[2] + st.r[3]);
    #pragma unroll
    for (int i = 0; i < 4; i++) {
        const float I = Ip[i] + 6.0f * st.r[i] - 2.0f * rsum;
        const float vn0 = fmaf(0.04f * st.v[i], st.v[i],
                               fmaf(6.0f, st.v[i], 140.0f - st.u[i] + I));
        const float un0 = st.u[i] + P_A * fmaf(P_B, st.v[i], -st.u[i]);
        const bool  fired = (vn0 >= 30.0f);
        const float sp = fired ? 1.0f : 0.0f;        // SEL
        st.v[i]   = fired ? P_C : vn0;               // FSEL
        st.u[i]   = fired ? (un0 + P_D) : un0;       // FSEL
        st.r[i]   = fmaf(0.9f, st.r[i], 0.1f * sp);
        st.cnt[i] += sp;
    }
}

__global__ void __launch_bounds__(512, 1)
spiking_goal_selector_kernel(
    const float* __restrict__ pal_d_rate,   // (3072,)
    const float* __restrict__ neuromod_bias,// (4,)
    const float* __restrict__ W,            // (4, 3072) row-major
    const int*   __restrict__ substeps_p,   // scalar
    float* __restrict__ out, int out_size, int n_e)
{
    __shared__ float part[16];   // one partial per warp, float4-readable

    const int warp = threadIdx.x >> 5;
    const int lane = threadIdx.x & 31;

    // ---- hoist scalar loads: 2 LDGs on thread 0, consumed after barrier ----
    int    T = 0;
    float4 bias4 = make_float4(0.f, 0.f, 0.f, 0.f);
    if (threadIdx.x == 0) {
        T = *substeps_p;
        bias4 = *reinterpret_cast<const float4*>(neuromod_bias);
    }

    // ---- matvec (measured-best config): 16 warps, 4 per row,
    //      6 fully-unrolled float4 per lane -> whole W in one load wave ----
    const int row = warp >> 2;
    const int p   = warp & 3;
    const int nv4 = n_e >> 2;
    const int q   = nv4 >> 2;          // float4s per warp-slice (192)
    const float4* Wr = reinterpret_cast<const float4*>(W + (size_t)row * n_e) + p * q;
    const float4* xr = reinterpret_cast<const float4*>(pal_d_rate) + p * q;

    float s = 0.0f;
    #pragma unroll 6
    for (int i = lane; i < q; i += 32) {
        float4 w = Wr[i];
        float4 x = xr[i];
        s += w.x * x.x + w.y * x.y + w.z * x.z + w.w * x.w;
    }
    #pragma unroll
    for (int o = 16; o > 0; o >>= 1)
        s += __shfl_down_sync(0xffffffffu, s, o);
    if (lane == 0) part[warp] = s;
    __syncthreads();

    // ---- serial WTA dynamics on thread 0 (4 neurons, T steps) ----
    if (threadIdx.x == 0) {
        const float4* p4 = reinterpret_cast<const float4*>(part);
        float Ip[4];
        float m = 0.0f;
        #pragma unroll
        for (int i = 0; i < 4; i++) {
            const float4 v4 = p4[i];                 // LDS.128, one per row
            Ip[i] = (v4.x + v4.y) + (v4.z + v4.w);
            m += fabsf(Ip[i]);
        }
        m = m * 0.25f + 1e-8f;
        const float scale = (m > 1e-3f) ? (3.0f / m) : 0.0f;
        const float bias[4] = {bias4.x, bias4.y, bias4.z, bias4.w};
        #pragma unroll
        for (int i = 0; i < 4; i++)
            Ip[i] = fmaf(Ip[i], scale, fmaf(bias[i], 2.0f, I_TONIC));

        SimState st;
        #pragma unroll
        for (int i = 0; i < 4; i++) {
            st.v[i] = P_C; st.u[i] = P_B * P_C; st.r[i] = 0.0f; st.cnt[i] = 0.0f;
        }

        if (T == 30) {
            #pragma unroll 6
            for (int t = 0; t < 30; t++) sim_step(st, Ip);
        } else {
            for (int t = 0; t < T; t++) sim_step(st, Ip);
        }

        const float invT = 1.0f / (float)T;
        float4 rates;
        rates.x = st.cnt[0] * invT;
        rates.y = st.cnt[1] * invT;
        rates.z = st.cnt[2] * invT;
        rates.w = st.cnt[3] * invT;
        const float rsum2 = (rates.x + rates.y) + (rates.z + rates.w);

        int win = 0; float best = rates.x;
        if (rates.y > best) { best = rates.y; win = 1; }
        if (rates.z > best) { best = rates.z; win = 2; }
        if (rates.w > best) { best = rates.w; win = 3; }

        // Output layout: [rates(4), winner, confidence]
        if (out_size >= 6) {
            *reinterpret_cast<float4*>(out) = rates;
            out[4] = (float)win;
            out[5] = best / (rsum2 + 1e-8f);
        } else {
            float rr[4] = {rates.x, rates.y, rates.z, rates.w};
            for (int i = 0; i < 4 && i < out_size; i++) out[i] = rr[i];
            if (out_size > 4) out[4] = (float)win;
            if (out_size > 5) out[5] = best / (rsum2 + 1e-8f);
        }
    }
}

extern "C" void kernel_launch(void* const* d_in, const int* in_sizes, int n_in,
                              void* d_out, int out_size)
{
    const float* pal_d_rate    = (const float*)d_in[0];   // 3072
    const float* neuromod_bias = (const float*)d_in[1];   // 4
    const float* W_pald_goal   = (const float*)d_in[2];   // 4*3072
    const int*   substeps      = (const int*)  d_in[3];   // 1
    float* out = (float*)d_out;
    const int n_e = in_sizes[0];

    spiking_goal_selector_kernel<<<1, 512>>>(
        pal_d_rate, neuromod_bias, W_pald_goal, substeps, out, out_size, n_e);
}

// round 6
// speedup vs baseline: 1.1062x; 1.0044x over previous
#include <cuda_runtime.h>

// Izhikevich RS constants (match reference)
#define P_A 0.02f
#define P_B 0.2f
#define P_C (-65.0f)
#define P_D 8.0f
#define I_TONIC (-3.0f)
// W_rec: diag = 4.0, offdiag = -2.0  =>  I_rec[i] = 6*r[i] - 2*sum(r)

#define SIM_TID 480   // warp 15, lane 0: runs the serial sim + holds T/bias

struct SimState {
    float v[4], u[4], r[4], cnt[4];
};

__device__ __forceinline__ void sim_step(SimState& st, const float* __restrict__ Ip)
{
    const float rsum = (st.r[0] + st.r[1]) + (st.r[2] + st.r[3]);
    #pragma unroll
    for (int i = 0; i < 4; i++) {
        const float I = Ip[i] + 6.0f * st.r[i] - 2.0f * rsum;
        const float vn0 = fmaf(0.04f * st.v[i], st.v[i],
                               fmaf(6.0f, st.v[i], 140.0f - st.u[i] + I));
        const float un0 = st.u[i] + P_A * fmaf(P_B, st.v[i], -st.u[i]);
        const bool  fired = (vn0 >= 30.0f);
        const float sp = fired ? 1.0f : 0.0f;
        st.v[i]   = fired ? P_C : vn0;
        st.u[i]   = fired ? (un0 + P_D) : un0;
        st.r[i]   = fmaf(0.9f, st.r[i], 0.1f * sp);
        st.cnt[i] += sp;
    }
}

__global__ void __launch_bounds__(512, 1)
spiking_goal_selector_kernel(
    const float* __restrict__ pal_d_rate,   // (3072,)
    const float* __restrict__ neuromod_bias,// (4,)
    const float* __restrict__ W,            // (4, 3072) row-major
    const int*   __restrict__ substeps_p,   // scalar
    float* __restrict__ out, int out_size, int n_e)
{
    __shared__ float part[16];   // one partial per warp, float4-readable

    const int warp = threadIdx.x >> 5;
    const int lane = threadIdx.x & 31;

    // ---- scalar loads on the SIM thread (warp 15): warp 0's stream stays
    //      pure W/x so the block's load front starts immediately ----
    int    T = 0;
    float4 bias4 = make_float4(0.f, 0.f, 0.f, 0.f);
    if (threadIdx.x == SIM_TID) {
        T = *substeps_p;
        bias4 = *reinterpret_cast<const float4*>(neuromod_bias);
    }

    // ---- matvec (measured-best config): 16 warps, 4 per row,
    //      6 fully-unrolled float4 per lane -> whole W in one load wave ----
    const int row = warp >> 2;
    const int p   = warp & 3;
    const int nv4 = n_e >> 2;
    const int q   = nv4 >> 2;          // float4s per warp-slice (192)
    const float4* Wr = reinterpret_cast<const float4*>(W + (size_t)row * n_e) + p * q;
    const float4* xr = reinterpret_cast<const float4*>(pal_d_rate) + p * q;

    float s = 0.0f;
    #pragma unroll 6
    for (int i = lane; i < q; i += 32) {
        float4 w = Wr[i];
        float4 x = xr[i];
        s += w.x * x.x + w.y * x.y + w.z * x.z + w.w * x.w;
    }
    #pragma unroll
    for (int o = 16; o > 0; o >>= 1)
        s += __shfl_down_sync(0xffffffffu, s, o);
    if (lane == 0) part[warp] = s;
    __syncthreads();

    // ---- serial WTA dynamics on the sim thread (4 neurons, T steps) ----
    if (threadIdx.x == SIM_TID) {
        const float4* p4 = reinterpret_cast<const float4*>(part);
        float Ip[4];
        float m = 0.0f;
        #pragma unroll
        for (int i = 0; i < 4; i++) {
            const float4 v4 = p4[i];                 // LDS.128, one per row
            Ip[i] = (v4.x + v4.y) + (v4.z + v4.w);
            m += fabsf(Ip[i]);
        }
        m = m * 0.25f + 1e-8f;
        const float scale = (m > 1e-3f) ? (3.0f / m) : 0.0f;
        const float bias[4] = {bias4.x, bias4.y, bias4.z, bias4.w};
        #pragma unroll
        for (int i = 0; i < 4; i++)
            Ip[i] = fmaf(Ip[i], scale, fmaf(bias[i], 2.0f, I_TONIC));

        SimState st;
        #pragma unroll
        for (int i = 0; i < 4; i++) {
            st.v[i] = P_C; st.u[i] = P_B * P_C; st.r[i] = 0.0f; st.cnt[i] = 0.0f;
        }

        if (T == 30) {
            #pragma unroll 6
            for (int t = 0; t < 30; t++) sim_step(st, Ip);
        } else {
            for (int t = 0; t < T; t++) sim_step(st, Ip);
        }

        const float invT = 1.0f / (float)T;
        float4 rates;
        rates.x = st.cnt[0] * invT;
        rates.y = st.cnt[1] * invT;
        rates.z = st.cnt[2] * invT;
        rates.w = st.cnt[3] * invT;
        const float rsum2 = (rates.x + rates.y) + (rates.z + rates.w);

        int win = 0; float best = rates.x;
        if (rates.y > best) { best = rates.y; win = 1; }
        if (rates.z > best) { best = rates.z; win = 2; }
        if (rates.w > best) { best = rates.w; win = 3; }

        // Output layout: [rates(4), winner, confidence]
        if (out_size >= 6) {
            *reinterpret_cast<float4*>(out) = rates;
            out[4] = (float)win;
            out[5] = best / (rsum2 + 1e-8f);
        } else {
            float rr[4] = {rates.x, rates.y, rates.z, rates.w};
            for (int i = 0; i < 4 && i < out_size; i++) out[i] = rr[i];
            if (out_size > 4) out[4] = (float)win;
            if (out_size > 5) out[5] = best / (rsum2 + 1e-8f);
        }
    }
}

extern "C" void kernel_launch(void* const* d_in, const int* in_sizes, int n_in,
                              void* d_out, int out_size)
{
    const float* pal_d_rate    = (const float*)d_in[0];   // 3072
    const float* neuromod_bias = (const float*)d_in[1];   // 4
    const float* W_pald_goal   = (const float*)d_in[2];   // 4*3072
    const int*   substeps      = (const int*)  d_in[3];   // 1
    float* out = (float*)d_out;
    const int n_e = in_sizes[0];

    spiking_goal_selector_kernel<<<1, 512>>>(
        pal_d_rate, neuromod_bias, W_pald_goal, substeps, out, out_size, n_e);
}